// round 12
// baseline (speedup 1.0000x reference)
#include <cuda_runtime.h>

#define N 512
#define TPB 128            // threads per block; each owns 4 consecutive columns
#define NWARPS (TPB / 32)  // 4

// Closed form for the Givens-rotation chain (rotations on columns (i,i+1),
// i = N-2 .. 0, theta index == i):
//   U[r][j]   = 0                                        for j > r+1
//   U[r][r+1] = s_r
//   U[r][j]   = c_r * c_{j-1} * prod_{m=j}^{r-1} (-s_m)  for j <= r   (c_{N-1}:=1)
//
// Block b computes rows r0..r0+3 (r0 = 4b). Thread t owns columns 4t..4t+3.
// T[j] = prod_{m=j}^{r0-1}(-s_m); the mask (j < r0) is thread-uniform
// (cols < r0  <=>  t < b). Engine: 3 local muls -> 5-step warp shuffle
// suffix scan -> 4 warp totals combined via one broadcast LDS.128.
// Exactly one __syncthreads. c_{j0-1} comes from a pre-barrier shfl_up
// (lane-0 threads recompute it directly) so the post-barrier path is just
// LDS(shW) + LDS.128(row consts) -> epilogue.
//
// CONVERGED FINAL: launch-overhead-bound (T_ovh ~5000 cyc rollout dominates,
// all pipes <3%). 11 structural variants measured; this is the harness-best.
__global__ __launch_bounds__(TPB) void unitary_closed_form_kernel(
    const float* __restrict__ thetas,  // K = N-1 = 511 angles
    float* __restrict__ out)           // N x N row-major fp32
{
    __shared__ __align__(16) float sh_s[N];
    __shared__ __align__(16) float sh_c[N];
    __shared__ __align__(16) float shW[NWARPS];

    const int t    = threadIdx.x;
    const int lane = t & 31;
    const int w    = t >> 5;
    const int b    = blockIdx.x;
    const int r0   = b * 4;
    const int j0   = t * 4;

    // sincos of this thread's 4 thetas (clamped load; fix col N-1).
    float s[4], c[4];
    #pragma unroll
    for (int k = 0; k < 4; ++k) {
        const int jj = j0 + k;
        __sincosf(__ldg(thetas + ((jj < N - 1) ? jj : (N - 2))), &s[k], &c[k]);
    }
    if (t == TPB - 1) { s[3] = 0.0f; c[3] = 1.0f; }   // column N-1

    reinterpret_cast<float4*>(sh_s)[t] = make_float4(s[0], s[1], s[2], s[3]);
    reinterpret_cast<float4*>(sh_c)[t] = make_float4(c[0], c[1], c[2], c[3]);

    // Left-neighbor cosine c_{j0-1}, PRE-barrier: shuffle from thread t-1;
    // lane-0 threads (t = 32,64,96) recompute directly; t = 0 uses 1.
    float cm1 = __shfl_up_sync(0xffffffffu, c[3], 1);
    if (lane == 0) {
        cm1 = 1.0f;
        if (t > 0) {
            float ss, cc;
            __sincosf(__ldg(thetas + (j0 - 1)), &ss, &cc);
            cm1 = cc;
        }
    }

    // a_k = -s_k if this thread's columns are < r0 (t < b), else 1.
    const bool on = (t < b);
    const float a0 = on ? -s[0] : 1.0f;
    const float a1 = on ? -s[1] : 1.0f;
    const float a2 = on ? -s[2] : 1.0f;
    const float a3 = on ? -s[3] : 1.0f;

    // Local suffix products u_k = prod_{m=k}^{3} a_m.
    const float u3 = a3;
    const float u2 = a2 * a3;
    const float u1 = a1 * u2;
    const float u0 = a0 * u1;   // thread total

    // Warp suffix-product scan of thread totals: P = prod_{l=lane}^{31} L_l.
    float P = u0;
    #pragma unroll
    for (int off = 1; off < 32; off <<= 1) {
        float v = __shfl_down_sync(0xffffffffu, P, off);
        if (lane + off < 32) P *= v;
    }
    if (lane == 0) shW[w] = P;   // full-warp product

    __syncthreads();             // covers sh_s, sh_c, shW

    // Exclusive-beyond-thread term:
    //   within warp: shfl_down(P,1), lane 31 -> 1
    //   beyond warp: prod of shW[w'] for w' > w (one broadcast LDS.128)
    float Pe = __shfl_down_sync(0xffffffffu, P, 1);
    if (lane == 31) Pe = 1.0f;
    const float4 q = reinterpret_cast<const float4*>(shW)[0];
    float e = 1.0f;
    if (w < 1) e *= q.y;
    if (w < 2) e *= q.z;
    if (w < 3) e *= q.w;
    const float E = Pe * e;

    // x_k = c_{j-1} * prod_{m=j}^{r0-1}(-s_m).
    float xv[4];
    xv[0] = cm1  * (u0 * E);
    xv[1] = c[0] * (u1 * E);
    xv[2] = c[1] * (u2 * E);
    xv[3] = c[2] * (u3 * E);

    // Row constants for rows r0..r0+3 (one broadcast LDS.128 each; r0 = 4b).
    const float4 cr4 = reinterpret_cast<const float4*>(sh_c)[b];
    const float4 sr4 = reinterpret_cast<const float4*>(sh_s)[b];
    const float crk[4] = {cr4.x, cr4.y, cr4.z, cr4.w};
    const float srk[4] = {sr4.x, sr4.y, sr4.z, sr4.w};

    float4* orow = reinterpret_cast<float4*>(out + (size_t)r0 * N) + t;
    #pragma unroll
    for (int rr = 0; rr < 4; ++rr) {
        const int r = r0 + rr;
        float v[4];
        #pragma unroll
        for (int k = 0; k < 4; ++k) {
            const int jj = j0 + k;
            float val;
            if (jj <= r) {
                val = crk[rr] * xv[k];   // c_{N-1} == 1 handles r = N-1
                xv[k] *= -srk[rr];       // advance ONLY once activated
            } else if (jj == r + 1) {
                val = srk[rr];           // superdiagonal: s_r
            } else {
                val = 0.0f;
            }
            v[k] = val;
        }
        *orow = make_float4(v[0], v[1], v[2], v[3]);   // coalesced STG.128
        orow += N / 4;
    }
}

extern "C" void kernel_launch(void* const* d_in, const int* in_sizes, int n_in,
                              void* d_out, int out_size) {
    (void)in_sizes; (void)n_in; (void)out_size;
    const float* thetas = (const float*)d_in[0];
    float* out = (float*)d_out;
    unitary_closed_form_kernel<<<N / 4, TPB>>>(thetas, out);
}

// round 13
// speedup vs baseline: 1.0542x; 1.0542x over previous
#include <cuda_runtime.h>

#define N 512
#define TPB 128            // threads per block; each owns 4 consecutive columns
#define NWARPS (TPB / 32)  // 4

// Closed form for the Givens-rotation chain (rotations on columns (i,i+1),
// i = N-2 .. 0, theta index == i):
//   U[r][j]   = 0                                        for j > r+1
//   U[r][r+1] = s_r
//   U[r][j]   = c_r * c_{j-1} * prod_{m=j}^{r-1} (-s_m)  for j <= r   (c_{N-1}:=1)
//
// Block b computes rows r0..r0+3 (r0 = 4b). Thread t owns columns 4t..4t+3.
// T[j] = prod_{m=j}^{r0-1}(-s_m); the mask (j < r0) is thread-uniform
// (cols < r0  <=>  t < b). Engine: 3 local muls -> 5-step warp shuffle
// suffix scan -> 4 warp totals combined via one broadcast LDS.128.
// Exactly one __syncthreads. c_{j0-1} comes from a pre-barrier shfl_up
// (lane-0 threads recompute it directly) so the post-barrier path is just
// LDS(shW) + LDS.128(row consts) -> epilogue.
//
// CONVERGED FINAL: launch-overhead-bound (T_ovh ~5000 cyc rollout dominates,
// all pipes <3%, run-to-run noise +-0.2us exceeds all structural deltas).
// 12 rounds / 10 structural variants measured; this is the harness-best.
__global__ __launch_bounds__(TPB) void unitary_closed_form_kernel(
    const float* __restrict__ thetas,  // K = N-1 = 511 angles
    float* __restrict__ out)           // N x N row-major fp32
{
    __shared__ __align__(16) float sh_s[N];
    __shared__ __align__(16) float sh_c[N];
    __shared__ __align__(16) float shW[NWARPS];

    const int t    = threadIdx.x;
    const int lane = t & 31;
    const int w    = t >> 5;
    const int b    = blockIdx.x;
    const int r0   = b * 4;
    const int j0   = t * 4;

    // sincos of this thread's 4 thetas (clamped load; fix col N-1).
    float s[4], c[4];
    #pragma unroll
    for (int k = 0; k < 4; ++k) {
        const int jj = j0 + k;
        __sincosf(__ldg(thetas + ((jj < N - 1) ? jj : (N - 2))), &s[k], &c[k]);
    }
    if (t == TPB - 1) { s[3] = 0.0f; c[3] = 1.0f; }   // column N-1

    reinterpret_cast<float4*>(sh_s)[t] = make_float4(s[0], s[1], s[2], s[3]);
    reinterpret_cast<float4*>(sh_c)[t] = make_float4(c[0], c[1], c[2], c[3]);

    // Left-neighbor cosine c_{j0-1}, PRE-barrier: shuffle from thread t-1;
    // lane-0 threads (t = 32,64,96) recompute directly; t = 0 uses 1.
    float cm1 = __shfl_up_sync(0xffffffffu, c[3], 1);
    if (lane == 0) {
        cm1 = 1.0f;
        if (t > 0) {
            float ss, cc;
            __sincosf(__ldg(thetas + (j0 - 1)), &ss, &cc);
            cm1 = cc;
        }
    }

    // a_k = -s_k if this thread's columns are < r0 (t < b), else 1.
    const bool on = (t < b);
    const float a0 = on ? -s[0] : 1.0f;
    const float a1 = on ? -s[1] : 1.0f;
    const float a2 = on ? -s[2] : 1.0f;
    const float a3 = on ? -s[3] : 1.0f;

    // Local suffix products u_k = prod_{m=k}^{3} a_m.
    const float u3 = a3;
    const float u2 = a2 * a3;
    const float u1 = a1 * u2;
    const float u0 = a0 * u1;   // thread total

    // Warp suffix-product scan of thread totals: P = prod_{l=lane}^{31} L_l.
    float P = u0;
    #pragma unroll
    for (int off = 1; off < 32; off <<= 1) {
        float v = __shfl_down_sync(0xffffffffu, P, off);
        if (lane + off < 32) P *= v;
    }
    if (lane == 0) shW[w] = P;   // full-warp product

    __syncthreads();             // covers sh_s, sh_c, shW

    // Exclusive-beyond-thread term:
    //   within warp: shfl_down(P,1), lane 31 -> 1
    //   beyond warp: prod of shW[w'] for w' > w (one broadcast LDS.128)
    float Pe = __shfl_down_sync(0xffffffffu, P, 1);
    if (lane == 31) Pe = 1.0f;
    const float4 q = reinterpret_cast<const float4*>(shW)[0];
    float e = 1.0f;
    if (w < 1) e *= q.y;
    if (w < 2) e *= q.z;
    if (w < 3) e *= q.w;
    const float E = Pe * e;

    // x_k = c_{j-1} * prod_{m=j}^{r0-1}(-s_m).
    float xv[4];
    xv[0] = cm1  * (u0 * E);
    xv[1] = c[0] * (u1 * E);
    xv[2] = c[1] * (u2 * E);
    xv[3] = c[2] * (u3 * E);

    // Row constants for rows r0..r0+3 (one broadcast LDS.128 each; r0 = 4b).
    const float4 cr4 = reinterpret_cast<const float4*>(sh_c)[b];
    const float4 sr4 = reinterpret_cast<const float4*>(sh_s)[b];
    const float crk[4] = {cr4.x, cr4.y, cr4.z, cr4.w};
    const float srk[4] = {sr4.x, sr4.y, sr4.z, sr4.w};

    float4* orow = reinterpret_cast<float4*>(out + (size_t)r0 * N) + t;
    #pragma unroll
    for (int rr = 0; rr < 4; ++rr) {
        const int r = r0 + rr;
        float v[4];
        #pragma unroll
        for (int k = 0; k < 4; ++k) {
            const int jj = j0 + k;
            float val;
            if (jj <= r) {
                val = crk[rr] * xv[k];   // c_{N-1} == 1 handles r = N-1
                xv[k] *= -srk[rr];       // advance ONLY once activated
            } else if (jj == r + 1) {
                val = srk[rr];           // superdiagonal: s_r
            } else {
                val = 0.0f;
            }
            v[k] = val;
        }
        *orow = make_float4(v[0], v[1], v[2], v[3]);   // coalesced STG.128
        orow += N / 4;
    }
}

extern "C" void kernel_launch(void* const* d_in, const int* in_sizes, int n_in,
                              void* d_out, int out_size) {
    (void)in_sizes; (void)n_in; (void)out_size;
    const float* thetas = (const float*)d_in[0];
    float* out = (float*)d_out;
    unitary_closed_form_kernel<<<N / 4, TPB>>>(thetas, out);
}